// round 1
// baseline (speedup 1.0000x reference)
#include <cuda_runtime.h>
#include <cuda_bf16.h>
#include <cstdint>

// Cross-stitch: per-channel 2x2 mix.
//   out_a[n,c,h,w] = w[c,0,0]*x_a + w[c,0,1]*x_b
//   out_b[n,c,h,w] = w[c,1,0]*x_a + w[c,1,1]*x_b
// Shapes: x_a, x_b: [32, 256, 64, 64] fp32. weights: [256, 2, 2] fp32.
// Output: out_a followed by out_b (2 * 32*256*64*64 floats).

static constexpr int N_ = 32;
static constexpr int C_ = 256;
static constexpr int HW_ = 64 * 64;                 // 4096 floats per channel row
static constexpr long long TOT = (long long)N_ * C_ * HW_;   // 33,554,432
static constexpr int HW4 = HW_ / 4;                 // 1024 float4 per channel row
static constexpr long long TOT4 = TOT / 4;          // 8,388,608 float4

__global__ __launch_bounds__(256)
void cross_stitch_kernel(const float4* __restrict__ xa,
                         const float4* __restrict__ xb,
                         const float*  __restrict__ w,   // [C,2,2]
                         float4* __restrict__ oa,
                         float4* __restrict__ ob)
{
    long long i4 = (long long)blockIdx.x * blockDim.x + threadIdx.x;
    if (i4 >= TOT4) return;

    // channel = (float index / 4096) % 256 ; float index = i4*4
    int c = (int)((i4 >> 10) & (C_ - 1));

    // weights per channel: w[c*4 + {0,1,2,3}] = {w00, w01, w10, w11}
    const float* wc = w + c * 4;
    float w00 = __ldg(wc + 0);
    float w01 = __ldg(wc + 1);
    float w10 = __ldg(wc + 2);
    float w11 = __ldg(wc + 3);

    float4 a = __ldg(xa + i4);
    float4 b = __ldg(xb + i4);

    float4 ra, rb;
    ra.x = fmaf(w00, a.x, w01 * b.x);
    ra.y = fmaf(w00, a.y, w01 * b.y);
    ra.z = fmaf(w00, a.z, w01 * b.z);
    ra.w = fmaf(w00, a.w, w01 * b.w);

    rb.x = fmaf(w10, a.x, w11 * b.x);
    rb.y = fmaf(w10, a.y, w11 * b.y);
    rb.z = fmaf(w10, a.z, w11 * b.z);
    rb.w = fmaf(w10, a.w, w11 * b.w);

    oa[i4] = ra;
    ob[i4] = rb;
}

extern "C" void kernel_launch(void* const* d_in, const int* in_sizes, int n_in,
                              void* d_out, int out_size)
{
    const float4* xa = (const float4*)d_in[0];
    const float4* xb = (const float4*)d_in[1];
    const float*  w  = (const float*)d_in[2];

    float4* oa = (float4*)d_out;
    float4* ob = oa + TOT4;   // out_b follows out_a

    int threads = 256;
    long long blocks = (TOT4 + threads - 1) / threads;
    cross_stitch_kernel<<<(unsigned)blocks, threads>>>(xa, xb, w, oa, ob);
}